// round 9
// baseline (speedup 1.0000x reference)
#include <cuda_runtime.h>
#include <cuda_bf16.h>
#include <cstdint>
#include <cstddef>

// Collapsed VGGT pipeline:
//   depth[t] = patches[t] . (W_tok @ W_depth)  +  coords[t] . (W_pos @ W_depth)
//            + (b_tok + b_pos) . W_depth + b_depth
// The ragged scatter/gather in the reference is an identity on valid tokens.
//
// R9: the dot kernel runs at the demonstrated DRAM stream ceiling (~5.5 TB/s,
// path-independent LDG==TMA; L2 persistence is blocked by the harness's
// device-limit guard). The only remaining cost is the serialized prep kernel
// (~2.2us of the 25.1us total). PDL overlaps prep under the dot kernel's
// initial patch loads, which don't depend on prep's output.

#define PATCH_DIM 768
#define EMBED_DIM 256
#define COORD_DIM 3

// scratch: [0..767] = v (W_tok@W_depth), [768..770] = u (W_pos@W_depth), [771] = c
__device__ __align__(16) float g_scratch[772];

// ---------------- prep: one warp per output element of v/u ----------------
__global__ __launch_bounds__(256)
void vggt_prep_kernel(const float* __restrict__ W_tok,
                      const float* __restrict__ b_tok,
                      const float* __restrict__ W_pos,
                      const float* __restrict__ b_pos,
                      const float* __restrict__ W_depth,
                      const float* __restrict__ b_depth) {
    int w    = (blockIdx.x * blockDim.x + threadIdx.x) >> 5;
    int lane = threadIdx.x & 31;
    if (w <= PATCH_DIM + COORD_DIM) {        // 0..771
        float s = 0.f;
        if (w <= PATCH_DIM + COORD_DIM - 1) {
            const float* base = (w < PATCH_DIM)
                ? (W_tok + (size_t)w * EMBED_DIM)
                : (W_pos + (size_t)(w - PATCH_DIM) * EMBED_DIM);
            const float4* __restrict__ r4 = (const float4*)base;
            const float4* __restrict__ d4 = (const float4*)W_depth;
            #pragma unroll
            for (int k = 0; k < 2; k++) {
                float4 a = r4[lane + 32 * k];
                float4 b = d4[lane + 32 * k];
                s = fmaf(a.x, b.x, s);
                s = fmaf(a.y, b.y, s);
                s = fmaf(a.z, b.z, s);
                s = fmaf(a.w, b.w, s);
            }
        } else {
            #pragma unroll
            for (int k = 0; k < 8; k++) {
                int j = lane + 32 * k;
                s = fmaf(b_tok[j] + b_pos[j], W_depth[j], s);
            }
        }

        #pragma unroll
        for (int off = 16; off; off >>= 1)
            s += __shfl_down_sync(0xffffffffu, s, off);

        if (lane == 0) {
            if (w == PATCH_DIM + COORD_DIM) s += b_depth[0];
            g_scratch[w] = s;
        }
    }
    // Signal dependent kernel may launch (its gridsync still orders our stores).
    cudaTriggerProgrammaticLaunchCompletion();
}

// Streaming loads (non-coherent path; hint harmless even though the persisting
// carveout is 0 in this harness).
__device__ __forceinline__ float4 ldg_nc4(const float4* p) {
    float4 v;
    asm volatile("ld.global.nc.v4.f32 {%0,%1,%2,%3}, [%4];"
                 : "=f"(v.x), "=f"(v.y), "=f"(v.z), "=f"(v.w) : "l"(p));
    return v;
}
__device__ __forceinline__ float ldg_nc1(const float* p) {
    float v;
    asm volatile("ld.global.nc.f32 %0, [%1];" : "=f"(v) : "l"(p));
    return v;
}

// ---------------- main: warp-per-row dot, PDL-overlapped ----------------
__global__ __launch_bounds__(256, 8)
void vggt_dot_kernel(const float4* __restrict__ patches,
                     const float* __restrict__ coords,
                     float* __restrict__ out, int T) {
    __shared__ float4 sv[PATCH_DIM / 4];   // 3 KB: v (block-local copy)
    __shared__ float  su[4];               // u[0..2], c

    int tid  = threadIdx.x;
    int warp = (blockIdx.x * blockDim.x + tid) >> 5;
    int lane = tid & 31;
    bool active = warp < T;
    int  w   = active ? warp : 0;

    const float4* __restrict__ row = patches + (size_t)w * (PATCH_DIM / 4);

    // Front-batch the per-lane DRAM stream BEFORE waiting on prep — this is
    // the work PDL overlaps with the prep kernel.
    float4 a0 = ldg_nc4(row + lane);
    float4 a1 = ldg_nc4(row + lane + 32);
    float4 a2 = ldg_nc4(row + lane + 64);
    float4 a3 = ldg_nc4(row + lane + 96);
    float4 a4 = ldg_nc4(row + lane + 128);
    float4 a5 = ldg_nc4(row + lane + 160);
    float  cv = (lane < COORD_DIM)
              ? ldg_nc1(coords + (size_t)w * COORD_DIM + lane) : 0.f;

    // Wait for prep's g_scratch writes to be visible.
    cudaGridDependencySynchronize();

    if (tid < PATCH_DIM / 4) sv[tid] = ((const float4*)g_scratch)[tid];
    if (tid < 4)             su[tid] = g_scratch[PATCH_DIM + tid];
    __syncthreads();

    float s0 = 0.f, s1 = 0.f;
    {
        float4 b = sv[lane];
        s0 = fmaf(a0.x, b.x, s0); s1 = fmaf(a0.y, b.y, s1);
        s0 = fmaf(a0.z, b.z, s0); s1 = fmaf(a0.w, b.w, s1);
    }
    {
        float4 b = sv[lane + 32];
        s0 = fmaf(a1.x, b.x, s0); s1 = fmaf(a1.y, b.y, s1);
        s0 = fmaf(a1.z, b.z, s0); s1 = fmaf(a1.w, b.w, s1);
    }
    {
        float4 b = sv[lane + 64];
        s0 = fmaf(a2.x, b.x, s0); s1 = fmaf(a2.y, b.y, s1);
        s0 = fmaf(a2.z, b.z, s0); s1 = fmaf(a2.w, b.w, s1);
    }
    {
        float4 b = sv[lane + 96];
        s0 = fmaf(a3.x, b.x, s0); s1 = fmaf(a3.y, b.y, s1);
        s0 = fmaf(a3.z, b.z, s0); s1 = fmaf(a3.w, b.w, s1);
    }
    {
        float4 b = sv[lane + 128];
        s0 = fmaf(a4.x, b.x, s0); s1 = fmaf(a4.y, b.y, s1);
        s0 = fmaf(a4.z, b.z, s0); s1 = fmaf(a4.w, b.w, s1);
    }
    {
        float4 b = sv[lane + 160];
        s0 = fmaf(a5.x, b.x, s0); s1 = fmaf(a5.y, b.y, s1);
        s0 = fmaf(a5.z, b.z, s0); s1 = fmaf(a5.w, b.w, s1);
    }

    float s = s0 + s1;
    if (lane < COORD_DIM) s = fmaf(cv, su[lane], s);

    #pragma unroll
    for (int off = 16; off; off >>= 1)
        s += __shfl_down_sync(0xffffffffu, s, off);

    if (active && lane == 0)
        out[warp] = s + su[3];
}

extern "C" void kernel_launch(void* const* d_in, const int* in_sizes, int n_in,
                              void* d_out, int out_size) {
    // metadata order: counts, all_coords, all_patches, W_tok, b_tok,
    //                 W_pos, b_pos, W_depth, b_depth
    const float* all_coords  = (const float*)d_in[1];
    const float* all_patches = (const float*)d_in[2];
    const float* W_tok   = (const float*)d_in[3];
    const float* b_tok   = (const float*)d_in[4];
    const float* W_pos   = (const float*)d_in[5];
    const float* b_pos   = (const float*)d_in[6];
    const float* W_depth = (const float*)d_in[7];
    const float* b_depth = (const float*)d_in[8];
    float* out = (float*)d_out;

    int T = out_size;  // depth is [T, 1] fp32

    int prep_warps  = PATCH_DIM + COORD_DIM + 1;      // 772
    int prep_blocks = (prep_warps * 32 + 255) / 256;  // 97
    vggt_prep_kernel<<<prep_blocks, 256>>>(W_tok, b_tok, W_pos, b_pos, W_depth, b_depth);

    int warps_per_block = 256 / 32;
    int blocks = (T + warps_per_block - 1) / warps_per_block;

    // PDL: allow the dot kernel to launch while prep is still running; the
    // device-side cudaGridDependencySynchronize orders the g_scratch reads.
    cudaLaunchConfig_t cfg = {};
    cfg.gridDim  = dim3((unsigned)blocks, 1, 1);
    cfg.blockDim = dim3(256, 1, 1);
    cfg.dynamicSmemBytes = 0;
    cfg.stream = 0;
    cudaLaunchAttribute attr[1];
    attr[0].id = cudaLaunchAttributeProgrammaticStreamSerialization;
    attr[0].val.programmaticStreamSerializationAllowed = 1;
    cfg.attrs = attr;
    cfg.numAttrs = 1;
    cudaLaunchKernelEx(&cfg, vggt_dot_kernel,
                       (const float4*)all_patches, all_coords, out, T);
}

// round 11
// speedup vs baseline: 1.1648x; 1.1648x over previous
#include <cuda_runtime.h>
#include <cuda_bf16.h>
#include <cstdint>
#include <cstddef>

// Collapsed VGGT pipeline:
//   depth[t] = patches[t] . (W_tok @ W_depth)  +  coords[t] . (W_pos @ W_depth)
//            + (b_tok + b_pos) . W_depth + b_depth
// The ragged scatter/gather in the reference is an identity on valid tokens.
//
// R10/R11: dot kernel body is the proven R8 shape (22.9us, 5.55 TB/s, no
// spills). PDL overlaps prep + the 4988-block launch ramp under prep's
// execution, with cudaGridDependencySynchronize at the TOP of the dot kernel
// so no registers are live across the sync (R9's spill regression).

#define PATCH_DIM 768
#define EMBED_DIM 256
#define COORD_DIM 3

// scratch: [0..767] = v (W_tok@W_depth), [768..770] = u (W_pos@W_depth), [771] = c
__device__ __align__(16) float g_scratch[772];

// ---------------- prep: one warp per output element of v/u ----------------
__global__ __launch_bounds__(256)
void vggt_prep_kernel(const float* __restrict__ W_tok,
                      const float* __restrict__ b_tok,
                      const float* __restrict__ W_pos,
                      const float* __restrict__ b_pos,
                      const float* __restrict__ W_depth,
                      const float* __restrict__ b_depth) {
    int w    = (blockIdx.x * blockDim.x + threadIdx.x) >> 5;
    int lane = threadIdx.x & 31;
    if (w <= PATCH_DIM + COORD_DIM) {        // 0..771
        float s = 0.f;
        if (w <= PATCH_DIM + COORD_DIM - 1) {
            const float* base = (w < PATCH_DIM)
                ? (W_tok + (size_t)w * EMBED_DIM)
                : (W_pos + (size_t)(w - PATCH_DIM) * EMBED_DIM);
            const float4* __restrict__ r4 = (const float4*)base;
            const float4* __restrict__ d4 = (const float4*)W_depth;
            #pragma unroll
            for (int k = 0; k < 2; k++) {
                float4 a = r4[lane + 32 * k];
                float4 b = d4[lane + 32 * k];
                s = fmaf(a.x, b.x, s);
                s = fmaf(a.y, b.y, s);
                s = fmaf(a.z, b.z, s);
                s = fmaf(a.w, b.w, s);
            }
        } else {
            #pragma unroll
            for (int k = 0; k < 8; k++) {
                int j = lane + 32 * k;
                s = fmaf(b_tok[j] + b_pos[j], W_depth[j], s);
            }
        }

        #pragma unroll
        for (int off = 16; off; off >>= 1)
            s += __shfl_down_sync(0xffffffffu, s, off);

        if (lane == 0) {
            if (w == PATCH_DIM + COORD_DIM) s += b_depth[0];
            g_scratch[w] = s;
        }
    }
    // Allow the dependent dot kernel to begin launching; its top-of-kernel
    // cudaGridDependencySynchronize still orders our g_scratch stores.
    cudaTriggerProgrammaticLaunchCompletion();
}

// Streaming non-coherent loads.
__device__ __forceinline__ float4 ldg_nc4(const float4* p) {
    float4 v;
    asm volatile("ld.global.nc.v4.f32 {%0,%1,%2,%3}, [%4];"
                 : "=f"(v.x), "=f"(v.y), "=f"(v.z), "=f"(v.w) : "l"(p));
    return v;
}
__device__ __forceinline__ float ldg_nc1(const float* p) {
    float v;
    asm volatile("ld.global.nc.f32 %0, [%1];" : "=f"(v) : "l"(p));
    return v;
}

// ---------------- main: warp-per-row dot (R8 body, PDL-gated) ----------------
__global__ __launch_bounds__(256, 8)
void vggt_dot_kernel(const float4* __restrict__ patches,
                     const float* __restrict__ coords,
                     float* __restrict__ out, int T) {
    // Wait for prep BEFORE anything is live — zero register pressure here.
    cudaGridDependencySynchronize();

    __shared__ float4 sv[PATCH_DIM / 4];   // 3 KB: v (block-local copy)
    __shared__ float  su[4];               // u[0..2], c

    int tid = threadIdx.x;
    if (tid < PATCH_DIM / 4) sv[tid] = ((const float4*)g_scratch)[tid];
    if (tid < 4)             su[tid] = g_scratch[PATCH_DIM + tid];
    __syncthreads();

    int warp = (blockIdx.x * blockDim.x + tid) >> 5;
    int lane = tid & 31;
    if (warp >= T) return;

    const float4* __restrict__ row = patches + (size_t)warp * (PATCH_DIM / 4);

    // Front-batch the per-lane DRAM stream (fits the 32-reg budget).
    float4 a0 = ldg_nc4(row + lane);
    float4 a1 = ldg_nc4(row + lane + 32);
    float4 a2 = ldg_nc4(row + lane + 64);
    float4 a3 = ldg_nc4(row + lane + 96);
    float4 a4 = ldg_nc4(row + lane + 128);
    float4 a5 = ldg_nc4(row + lane + 160);
    float  cv = (lane < COORD_DIM)
              ? ldg_nc1(coords + (size_t)warp * COORD_DIM + lane) : 0.f;

    float s0 = 0.f, s1 = 0.f;
    {
        float4 b = sv[lane];
        s0 = fmaf(a0.x, b.x, s0); s1 = fmaf(a0.y, b.y, s1);
        s0 = fmaf(a0.z, b.z, s0); s1 = fmaf(a0.w, b.w, s1);
    }
    {
        float4 b = sv[lane + 32];
        s0 = fmaf(a1.x, b.x, s0); s1 = fmaf(a1.y, b.y, s1);
        s0 = fmaf(a1.z, b.z, s0); s1 = fmaf(a1.w, b.w, s1);
    }
    {
        float4 b = sv[lane + 64];
        s0 = fmaf(a2.x, b.x, s0); s1 = fmaf(a2.y, b.y, s1);
        s0 = fmaf(a2.z, b.z, s0); s1 = fmaf(a2.w, b.w, s1);
    }
    {
        float4 b = sv[lane + 96];
        s0 = fmaf(a3.x, b.x, s0); s1 = fmaf(a3.y, b.y, s1);
        s0 = fmaf(a3.z, b.z, s0); s1 = fmaf(a3.w, b.w, s1);
    }
    {
        float4 b = sv[lane + 128];
        s0 = fmaf(a4.x, b.x, s0); s1 = fmaf(a4.y, b.y, s1);
        s0 = fmaf(a4.z, b.z, s0); s1 = fmaf(a4.w, b.w, s1);
    }
    {
        float4 b = sv[lane + 160];
        s0 = fmaf(a5.x, b.x, s0); s1 = fmaf(a5.y, b.y, s1);
        s0 = fmaf(a5.z, b.z, s0); s1 = fmaf(a5.w, b.w, s1);
    }

    float s = s0 + s1;
    if (lane < COORD_DIM) s = fmaf(cv, su[lane], s);

    #pragma unroll
    for (int off = 16; off; off >>= 1)
        s += __shfl_down_sync(0xffffffffu, s, off);

    if (lane == 0)
        out[warp] = s + su[3];
}

extern "C" void kernel_launch(void* const* d_in, const int* in_sizes, int n_in,
                              void* d_out, int out_size) {
    // metadata order: counts, all_coords, all_patches, W_tok, b_tok,
    //                 W_pos, b_pos, W_depth, b_depth
    const float* all_coords  = (const float*)d_in[1];
    const float* all_patches = (const float*)d_in[2];
    const float* W_tok   = (const float*)d_in[3];
    const float* b_tok   = (const float*)d_in[4];
    const float* W_pos   = (const float*)d_in[5];
    const float* b_pos   = (const float*)d_in[6];
    const float* W_depth = (const float*)d_in[7];
    const float* b_depth = (const float*)d_in[8];
    float* out = (float*)d_out;

    int T = out_size;  // depth is [T, 1] fp32

    int prep_warps  = PATCH_DIM + COORD_DIM + 1;      // 772
    int prep_blocks = (prep_warps * 32 + 255) / 256;  // 97
    vggt_prep_kernel<<<prep_blocks, 256>>>(W_tok, b_tok, W_pos, b_pos, W_depth, b_depth);

    int warps_per_block = 256 / 32;
    int blocks = (T + warps_per_block - 1) / warps_per_block;

    // PDL: dot launches while prep runs; its top-of-kernel gridsync orders
    // the g_scratch reads. If the attribute is unsupported, this degrades to
    // normal serialized launch (== R8 behavior).
    cudaLaunchConfig_t cfg = {};
    cfg.gridDim  = dim3((unsigned)blocks, 1, 1);
    cfg.blockDim = dim3(256, 1, 1);
    cfg.dynamicSmemBytes = 0;
    cfg.stream = 0;
    cudaLaunchAttribute attr[1];
    attr[0].id = cudaLaunchAttributeProgrammaticStreamSerialization;
    attr[0].val.programmaticStreamSerializationAllowed = 1;
    cfg.attrs = attr;
    cfg.numAttrs = 1;
    cudaLaunchKernelEx(&cfg, vggt_dot_kernel,
                       (const float4*)all_patches, all_coords, out, T);
}